// round 1
// baseline (speedup 1.0000x reference)
#include <cuda_runtime.h>
#include <cuda_bf16.h>
#include <math.h>

// ---------------------------------------------------------------------------
// CleanGeneralDIT: 2-block DiT forward, fp32 baseline.
// x <- block(x) twice; each block: adaLN-mod self-attn(3D RoPE) + cross-attn + GELU MLP
// Shapes: B=1, L=3072, D=1024, H=16, HD=64, S=512, DFF=4096, NB=2
// ---------------------------------------------------------------------------

#define LQ 3072
#define DM 1024
#define NH 16
#define HD 64
#define SC 512
#define DFF 4096

// Scratch (device globals: allocation-free per harness rules)
__device__ float g_hx[LQ * DM];
__device__ float g_q [LQ * DM];
__device__ float g_k [LQ * DM];
__device__ float g_v [LQ * DM];
__device__ float g_o [LQ * DM];
__device__ float g_h1[LQ * DFF];
__device__ float g_scores[(long long)NH * LQ * LQ];   // 604 MB, reused for cross-attn
__device__ float g_mods[6 * DM];

// ---------------------------------------------------------------------------
// GEMM: C[M,N] = A[M,K] * op(B) (+bias) with epilogues.
// TRANSB=true : B is [N,K] row-major (C = A * B^T)   -- all weight GEMMs, Q*K^T
// TRANSB=false: B is [K,N] row-major (C = A * B)     -- P*V
// EPI: 0 = store, 1 = exact-GELU store, 2 = C += gate[n]*(acc+bias[n]) (residual)
// Batched over blockIdx.z with element strides sA/sB/sC.
// ---------------------------------------------------------------------------
template<bool TRANSB, int EPI>
__global__ __launch_bounds__(256)
void gemm_kernel(const float* __restrict__ A, const float* __restrict__ B,
                 const float* __restrict__ bias, const float* __restrict__ gate,
                 float* __restrict__ C,
                 int M, int N, int K, int lda, int ldb, int ldc,
                 long long sA, long long sB, long long sC)
{
    long long bz = blockIdx.z;
    A += bz * sA; B += bz * sB; C += bz * sC;

    const int m0 = blockIdx.y * 128;
    const int n0 = blockIdx.x * 128;

    __shared__ float As[16][132];   // pad: reduce STS bank conflicts for k-fast stores
    __shared__ float Bs[16][132];

    const int tid = threadIdx.x;
    const int tx = tid & 15, ty = tid >> 4;
    const int ry0 = ty * 4, ry1 = 64 + ty * 4;
    const int cx0 = tx * 4, cx1 = 64 + tx * 4;

    float acc[8][8];
#pragma unroll
    for (int i = 0; i < 8; i++)
#pragma unroll
        for (int j = 0; j < 8; j++) acc[i][j] = 0.f;

    for (int k0 = 0; k0 < K; k0 += 16) {
        // load A tile (k-fast mapping: 16 consecutive threads read 64B of one row)
#pragma unroll
        for (int e = 0; e < 8; e++) {
            int idx = tid + e * 256;
            int m = idx >> 4, kk = idx & 15;
            int gm = m0 + m, gk = k0 + kk;
            As[kk][m] = (gm < M && gk < K) ? A[(long long)gm * lda + gk] : 0.f;
        }
        // load B tile
#pragma unroll
        for (int e = 0; e < 8; e++) {
            int idx = tid + e * 256;
            if (TRANSB) {
                int n = idx >> 4, kk = idx & 15;
                int gn = n0 + n, gk = k0 + kk;
                Bs[kk][n] = (gn < N && gk < K) ? B[(long long)gn * ldb + gk] : 0.f;
            } else {
                int kk = idx >> 7, n = idx & 127;
                int gn = n0 + n, gk = k0 + kk;
                Bs[kk][n] = (gn < N && gk < K) ? B[(long long)gk * ldb + gn] : 0.f;
            }
        }
        __syncthreads();

#pragma unroll
        for (int kk = 0; kk < 16; kk++) {
            float a[8], b[8];
            *(float4*)&a[0] = *(const float4*)&As[kk][ry0];
            *(float4*)&a[4] = *(const float4*)&As[kk][ry1];
            *(float4*)&b[0] = *(const float4*)&Bs[kk][cx0];
            *(float4*)&b[4] = *(const float4*)&Bs[kk][cx1];
#pragma unroll
            for (int i = 0; i < 8; i++)
#pragma unroll
                for (int j = 0; j < 8; j++)
                    acc[i][j] = fmaf(a[i], b[j], acc[i][j]);
        }
        __syncthreads();
    }

    // epilogue
#pragma unroll
    for (int i = 0; i < 8; i++) {
        int m = m0 + ((i < 4) ? (ry0 + i) : (ry1 + i - 4));
        if (m >= M) continue;
#pragma unroll
        for (int j = 0; j < 8; j++) {
            int n = n0 + ((j < 4) ? (cx0 + j) : (cx1 + j - 4));
            if (n >= N) continue;
            float val = acc[i][j];
            if (bias) val += bias[n];
            if (EPI == 1)
                val = 0.5f * val * (1.f + erff(val * 0.70710678118654752f));
            long long off = (long long)m * ldc + n;
            if (EPI == 2) {
                float g = gate ? gate[n] : 1.f;
                C[off] += g * val;
            } else {
                C[off] = val;
            }
        }
    }
}

// ---------------------------------------------------------------------------
// LayerNorm (eps 1e-6) with optional adaLN modulation: y = ln(x)*(1+sc)+sh
// One block per row (D=1024), 256 threads, float4.
// ---------------------------------------------------------------------------
__global__ __launch_bounds__(256)
void ln_kernel(const float* __restrict__ x, float* __restrict__ y,
               const float* __restrict__ sc, const float* __restrict__ sh)
{
    __shared__ float r1[256], r2[256];
    int row = blockIdx.x, tid = threadIdx.x;
    const float4* xr = (const float4*)(x + (long long)row * DM);
    float4 v = xr[tid];
    float s  = v.x + v.y + v.z + v.w;
    float sq = v.x * v.x + v.y * v.y + v.z * v.z + v.w * v.w;
    r1[tid] = s; r2[tid] = sq;
    __syncthreads();
    for (int st = 128; st > 0; st >>= 1) {
        if (tid < st) { r1[tid] += r1[tid + st]; r2[tid] += r2[tid + st]; }
        __syncthreads();
    }
    float mean = r1[0] * (1.f / DM);
    float var  = r2[0] * (1.f / DM) - mean * mean;
    float inv  = rsqrtf(var + 1e-6f);

    float a0 = (v.x - mean) * inv;
    float a1 = (v.y - mean) * inv;
    float a2 = (v.z - mean) * inv;
    float a3 = (v.w - mean) * inv;
    float4 o;
    int d = tid * 4;
    if (sc) {
        o.x = a0 * (1.f + sc[d + 0]) + sh[d + 0];
        o.y = a1 * (1.f + sc[d + 1]) + sh[d + 1];
        o.z = a2 * (1.f + sc[d + 2]) + sh[d + 2];
        o.w = a3 * (1.f + sc[d + 3]) + sh[d + 3];
    } else {
        o.x = a0; o.y = a1; o.z = a2; o.w = a3;
    }
    ((float4*)(y + (long long)row * DM))[tid] = o;
}

// ---------------------------------------------------------------------------
// 3D RoPE on q and k in place. rope[l][d] are angles, head dim 64, rot_half.
// Thread handles pair (d, d+32) of one (l, h).
// ---------------------------------------------------------------------------
__global__ void rope_kernel(float* __restrict__ q, float* __restrict__ k,
                            const float* __restrict__ rope)
{
    int idx = blockIdx.x * blockDim.x + threadIdx.x;
    if (idx >= LQ * NH * 32) return;
    int d = idx & 31;
    int h = (idx >> 5) & (NH - 1);
    int l = idx >> 9;
    const float* rl = rope + (long long)l * HD;
    float c1 = cosf(rl[d]),      s1 = sinf(rl[d]);
    float c2 = cosf(rl[d + 32]), s2 = sinf(rl[d + 32]);
    long long o = (long long)l * DM + h * HD + d;
    float q1 = q[o], q2 = q[o + 32];
    q[o]      = q1 * c1 - q2 * s1;
    q[o + 32] = q2 * c2 + q1 * s2;
    float k1 = k[o], k2 = k[o + 32];
    k[o]      = k1 * c1 - k2 * s1;
    k[o + 32] = k2 * c2 + k1 * s2;
}

// ---------------------------------------------------------------------------
// adaLN GEMV: out[6144] = adaW_i @ t + adab_i. One warp per output row.
// ---------------------------------------------------------------------------
__global__ __launch_bounds__(256)
void ada_kernel(const float* __restrict__ W, const float* __restrict__ b,
                const float* __restrict__ t, float* __restrict__ out)
{
    int warp = threadIdx.x >> 5, lane = threadIdx.x & 31;
    int row = blockIdx.x * 8 + warp;
    const float* wr = W + (long long)row * DM;
    float s = 0.f;
    for (int c = lane; c < DM; c += 32) s = fmaf(wr[c], t[c], s);
#pragma unroll
    for (int o = 16; o > 0; o >>= 1) s += __shfl_xor_sync(0xFFFFFFFFu, s, o);
    if (lane == 0) out[row] = s + b[row];
}

// ---------------------------------------------------------------------------
// Row softmax with scale, row cached in shared (len <= 3072).
// ---------------------------------------------------------------------------
__global__ __launch_bounds__(256)
void softmax_kernel(float* __restrict__ S, int len, float scale)
{
    __shared__ float buf[LQ];
    __shared__ float red[256];
    long long row = blockIdx.x;
    float* p = S + row * (long long)len;
    int tid = threadIdx.x;

    float mx = -1e30f;
    for (int i = tid; i < len; i += 256) {
        float v = p[i] * scale;
        buf[i] = v;
        mx = fmaxf(mx, v);
    }
    red[tid] = mx;
    __syncthreads();
    for (int st = 128; st > 0; st >>= 1) {
        if (tid < st) red[tid] = fmaxf(red[tid], red[tid + st]);
        __syncthreads();
    }
    mx = red[0];
    __syncthreads();

    float sum = 0.f;
    for (int i = tid; i < len; i += 256) {
        float e = __expf(buf[i] - mx);
        buf[i] = e;
        sum += e;
    }
    red[tid] = sum;
    __syncthreads();
    for (int st = 128; st > 0; st >>= 1) {
        if (tid < st) red[tid] += red[tid + st];
        __syncthreads();
    }
    float invs = 1.f / red[0];
    for (int i = tid; i < len; i += 256) p[i] = buf[i] * invs;
}

// ---------------------------------------------------------------------------
// Host-side launch helpers
// ---------------------------------------------------------------------------
static inline void gemm_nt(const float* A, const float* B, const float* bias,
                           const float* gate, float* C, int M, int N, int K,
                           int lda, int ldb, int ldc, int epi,
                           long long sA = 0, long long sB = 0, long long sC = 0,
                           int batch = 1)
{
    dim3 grid((N + 127) / 128, (M + 127) / 128, batch);
    if (epi == 0)      gemm_kernel<true, 0><<<grid, 256>>>(A, B, bias, gate, C, M, N, K, lda, ldb, ldc, sA, sB, sC);
    else if (epi == 1) gemm_kernel<true, 1><<<grid, 256>>>(A, B, bias, gate, C, M, N, K, lda, ldb, ldc, sA, sB, sC);
    else               gemm_kernel<true, 2><<<grid, 256>>>(A, B, bias, gate, C, M, N, K, lda, ldb, ldc, sA, sB, sC);
}

static inline void gemm_nn(const float* A, const float* B, float* C,
                           int M, int N, int K, int lda, int ldb, int ldc,
                           long long sA, long long sB, long long sC, int batch)
{
    dim3 grid((N + 127) / 128, (M + 127) / 128, batch);
    gemm_kernel<false, 0><<<grid, 256>>>(A, B, nullptr, nullptr, C, M, N, K, lda, ldb, ldc, sA, sB, sC);
}

extern "C" void kernel_launch(void* const* d_in, const int* in_sizes, int n_in,
                              void* d_out, int out_size)
{
    const float* x_in  = (const float*)d_in[0];
    const float* temb  = (const float*)d_in[1];
    const float* ctx   = (const float*)d_in[2];
    const float* rope  = (const float*)d_in[3];
    const float* adaW  = (const float*)d_in[4];
    const float* adab  = (const float*)d_in[5];
    const float* sqW   = (const float*)d_in[6];
    const float* skW   = (const float*)d_in[7];
    const float* svW   = (const float*)d_in[8];
    const float* soW   = (const float*)d_in[9];
    const float* sob   = (const float*)d_in[10];
    const float* cqW   = (const float*)d_in[11];
    const float* ckW   = (const float*)d_in[12];
    const float* cvW   = (const float*)d_in[13];
    const float* coW   = (const float*)d_in[14];
    const float* cob   = (const float*)d_in[15];
    const float* f1W   = (const float*)d_in[16];
    const float* f1b   = (const float*)d_in[17];
    const float* f2W   = (const float*)d_in[18];
    const float* f2b   = (const float*)d_in[19];

    float* x = (float*)d_out;   // x accumulates in the output buffer

    float *hx, *q, *k, *v, *o, *h1, *scores, *mods;
    cudaGetSymbolAddress((void**)&hx,     g_hx);
    cudaGetSymbolAddress((void**)&q,      g_q);
    cudaGetSymbolAddress((void**)&k,      g_k);
    cudaGetSymbolAddress((void**)&v,      g_v);
    cudaGetSymbolAddress((void**)&o,      g_o);
    cudaGetSymbolAddress((void**)&h1,     g_h1);
    cudaGetSymbolAddress((void**)&scores, g_scores);
    cudaGetSymbolAddress((void**)&mods,   g_mods);

    cudaMemcpyAsync(x, x_in, (size_t)LQ * DM * sizeof(float),
                    cudaMemcpyDeviceToDevice, 0);

    const float scale = 0.125f;   // HD^-0.5

    for (int i = 0; i < 2; i++) {
        const float* adaW_i = adaW + (long long)i * 6 * DM * DM;
        const float* adab_i = adab + (long long)i * 6 * DM;
        const float* sqW_i  = sqW + (long long)i * DM * DM;
        const float* skW_i  = skW + (long long)i * DM * DM;
        const float* svW_i  = svW + (long long)i * DM * DM;
        const float* soW_i  = soW + (long long)i * DM * DM;
        const float* sob_i  = sob + (long long)i * DM;
        const float* cqW_i  = cqW + (long long)i * DM * DM;
        const float* ckW_i  = ckW + (long long)i * DM * DM;
        const float* cvW_i  = cvW + (long long)i * DM * DM;
        const float* coW_i  = coW + (long long)i * DM * DM;
        const float* cob_i  = cob + (long long)i * DM;
        const float* f1W_i  = f1W + (long long)i * DFF * DM;
        const float* f1b_i  = f1b + (long long)i * DFF;
        const float* f2W_i  = f2W + (long long)i * DM * DFF;
        const float* f2b_i  = f2b + (long long)i * DM;

        // adaLN modulations
        ada_kernel<<<6 * DM / 8, 256>>>(adaW_i, adab_i, temb, mods);
        const float* sh_msa = mods + 0 * DM;
        const float* sc_msa = mods + 1 * DM;
        const float* g_msa  = mods + 2 * DM;
        const float* sh_mlp = mods + 3 * DM;
        const float* sc_mlp = mods + 4 * DM;
        const float* g_mlp  = mods + 5 * DM;

        // ---- self attention ----
        ln_kernel<<<LQ, 256>>>(x, hx, sc_msa, sh_msa);
        gemm_nt(hx, sqW_i, nullptr, nullptr, q, LQ, DM, DM, DM, DM, DM, 0);
        gemm_nt(hx, skW_i, nullptr, nullptr, k, LQ, DM, DM, DM, DM, DM, 0);
        gemm_nt(hx, svW_i, nullptr, nullptr, v, LQ, DM, DM, DM, DM, DM, 0);
        rope_kernel<<<(LQ * NH * 32 + 255) / 256, 256>>>(q, k, rope);

        // S_h = Q_h K_h^T  (batched over heads)
        gemm_nt(q, k, nullptr, nullptr, scores, LQ, LQ, HD, DM, DM, LQ, 0,
                HD, HD, (long long)LQ * LQ, NH);
        softmax_kernel<<<NH * LQ, 256>>>(scores, LQ, scale);
        // O_h = P_h V_h
        gemm_nn(scores, v, o, LQ, HD, LQ, LQ, DM, DM,
                (long long)LQ * LQ, HD, HD, NH);
        // x += g_msa * (O soW^T + sob)
        gemm_nt(o, soW_i, sob_i, g_msa, x, LQ, DM, DM, DM, DM, DM, 2);

        // ---- cross attention ----
        ln_kernel<<<LQ, 256>>>(x, hx, nullptr, nullptr);
        gemm_nt(hx,  cqW_i, nullptr, nullptr, q, LQ, DM, DM, DM, DM, DM, 0);
        gemm_nt(ctx, ckW_i, nullptr, nullptr, k, SC, DM, DM, DM, DM, DM, 0);
        gemm_nt(ctx, cvW_i, nullptr, nullptr, v, SC, DM, DM, DM, DM, DM, 0);
        gemm_nt(q, k, nullptr, nullptr, scores, LQ, SC, HD, DM, DM, SC, 0,
                HD, HD, (long long)LQ * SC, NH);
        softmax_kernel<<<NH * LQ, 256>>>(scores, SC, scale);
        gemm_nn(scores, v, o, LQ, HD, SC, SC, DM, DM,
                (long long)LQ * SC, HD, HD, NH);
        // x += O coW^T + cob  (no gate)
        gemm_nt(o, coW_i, cob_i, nullptr, x, LQ, DM, DM, DM, DM, DM, 2);

        // ---- MLP ----
        ln_kernel<<<LQ, 256>>>(x, hx, sc_mlp, sh_mlp);
        gemm_nt(hx, f1W_i, f1b_i, nullptr, h1, LQ, DFF, DM, DM, DM, DFF, 1);
        gemm_nt(h1, f2W_i, f2b_i, g_mlp, x, LQ, DM, DFF, DFF, DFF, DM, 2);
    }
}

// round 4
// speedup vs baseline: 4.0417x; 4.0417x over previous
#include <cuda_runtime.h>
#include <cuda_bf16.h>
#include <math.h>

// ---------------------------------------------------------------------------
// CleanGeneralDIT round 4: tf32 tensor-core GEMMs + fused flash attention.
// Shapes: B=1, L=3072, D=1024, H=16, HD=64, S=512, DFF=4096, NB=2
// No materialized score tensor (removes 604MB static scratch + softmax pass).
// ---------------------------------------------------------------------------

#define LQ 3072
#define DM 1024
#define NH 16
#define HD 64
#define SC 512
#define DFF 4096

#define BM 128
#define BK 16
#define SAS (BK + 4)   // gemm smem row stride: conflict-free fragment loads

// Scratch (device globals: allocation-free per harness rules) ~82 MB total
__device__ float g_hx[LQ * DM];
__device__ float g_q [LQ * DM];
__device__ float g_k [LQ * DM];
__device__ float g_v [LQ * DM];
__device__ float g_o [LQ * DM];
__device__ float g_h1[LQ * DFF];
__device__ float g_mods[6 * DM];

// ---------------------------------------------------------------------------
__device__ __forceinline__ unsigned f2tf32(float x) {
    unsigned y;
    asm("cvt.rna.tf32.f32 %0, %1;" : "=r"(y) : "f"(x));
    return y;
}

__device__ __forceinline__ void mma_tf32(float* c, const unsigned* a, const unsigned* b) {
    asm volatile(
        "mma.sync.aligned.m16n8k8.row.col.f32.tf32.tf32.f32 "
        "{%0,%1,%2,%3}, {%4,%5,%6,%7}, {%8,%9}, {%0,%1,%2,%3};"
        : "+f"(c[0]), "+f"(c[1]), "+f"(c[2]), "+f"(c[3])
        : "r"(a[0]), "r"(a[1]), "r"(a[2]), "r"(a[3]), "r"(b[0]), "r"(b[1]));
}

// ---------------------------------------------------------------------------
// Tensor-core GEMM: C[M,N] = A[M,K] * B^T (+epilogue). B is [N,K] row-major.
// EPI: 0 = store, 1 = exact-GELU(+bias) store, 2 = C += gate[n]*(acc+bias[n])
// Requires: M%128==0, N%128==0, K%16==0.
// ---------------------------------------------------------------------------
template<int EPI>
__global__ __launch_bounds__(256)
void gemm_tc(const float* __restrict__ A, const float* __restrict__ B,
             const float* __restrict__ bias, const float* __restrict__ gate,
             float* __restrict__ C,
             int M, int N, int K, int lda, int ldb, int ldc)
{
    const int m0 = blockIdx.y * BM;
    const int n0 = blockIdx.x * BM;

    __shared__ unsigned As[BM][SAS];
    __shared__ unsigned Bs[BM][SAS];

    const int tid  = threadIdx.x;
    const int warp = tid >> 5, lane = tid & 31;
    const int gid  = lane >> 2, tig = lane & 3;

    const int wm = (warp & 1) * 64;   // warp tile 64x32
    const int wn = (warp >> 1) * 32;

    float acc[4][4][4];
#pragma unroll
    for (int i = 0; i < 4; i++)
#pragma unroll
        for (int j = 0; j < 4; j++)
#pragma unroll
            for (int r = 0; r < 4; r++) acc[i][j][r] = 0.f;

    const int arow = tid >> 2;            // 0..63
    const int acg  = (tid & 3) << 2;      // 0,4,8,12
    float4 av0, av1, bv0, bv1;

#define LOAD_TILE(k0)                                                               \
    {                                                                               \
        av0 = *(const float4*)(A + (long long)(m0 + arow)      * lda + (k0) + acg); \
        av1 = *(const float4*)(A + (long long)(m0 + arow + 64) * lda + (k0) + acg); \
        bv0 = *(const float4*)(B + (long long)(n0 + arow)      * ldb + (k0) + acg); \
        bv1 = *(const float4*)(B + (long long)(n0 + arow + 64) * ldb + (k0) + acg); \
    }

#define STORE_TILE()                                                                                          \
    {                                                                                                         \
        *(uint4*)&As[arow][acg]      = make_uint4(f2tf32(av0.x), f2tf32(av0.y), f2tf32(av0.z), f2tf32(av0.w)); \
        *(uint4*)&As[arow + 64][acg] = make_uint4(f2tf32(av1.x), f2tf32(av1.y), f2tf32(av1.z), f2tf32(av1.w)); \
        *(uint4*)&Bs[arow][acg]      = make_uint4(f2tf32(bv0.x), f2tf32(bv0.y), f2tf32(bv0.z), f2tf32(bv0.w)); \
        *(uint4*)&Bs[arow + 64][acg] = make_uint4(f2tf32(bv1.x), f2tf32(bv1.y), f2tf32(bv1.z), f2tf32(bv1.w)); \
    }

    const int nK = K / BK;
    LOAD_TILE(0);
    STORE_TILE();
    __syncthreads();

    for (int it = 0; it < nK; ++it) {
        if (it + 1 < nK) LOAD_TILE((it + 1) * BK);

#pragma unroll
        for (int kc = 0; kc < BK; kc += 8) {
            unsigned af[4][4], bf[4][2];
#pragma unroll
            for (int mt = 0; mt < 4; mt++) {
                int mb = wm + mt * 16;
                af[mt][0] = As[mb + gid    ][kc + tig];
                af[mt][1] = As[mb + gid + 8][kc + tig];
                af[mt][2] = As[mb + gid    ][kc + tig + 4];
                af[mt][3] = As[mb + gid + 8][kc + tig + 4];
            }
#pragma unroll
            for (int nt = 0; nt < 4; nt++) {
                int nb = wn + nt * 8;
                bf[nt][0] = Bs[nb + gid][kc + tig];
                bf[nt][1] = Bs[nb + gid][kc + tig + 4];
            }
#pragma unroll
            for (int mt = 0; mt < 4; mt++)
#pragma unroll
                for (int nt = 0; nt < 4; nt++)
                    mma_tf32(acc[mt][nt], af[mt], bf[nt]);
        }
        __syncthreads();
        if (it + 1 < nK) {
            STORE_TILE();
            __syncthreads();
        }
    }

#undef LOAD_TILE
#undef STORE_TILE

#pragma unroll
    for (int mt = 0; mt < 4; mt++) {
#pragma unroll
        for (int nt = 0; nt < 4; nt++) {
            int r0 = m0 + wm + mt * 16 + gid;
            int c0 = n0 + wn + nt * 8 + tig * 2;
            float b0 = bias ? bias[c0]     : 0.f;
            float b1 = bias ? bias[c0 + 1] : 0.f;
#pragma unroll
            for (int half = 0; half < 2; half++) {
                int r = r0 + half * 8;
                float v0 = acc[mt][nt][half * 2 + 0] + b0;
                float v1 = acc[mt][nt][half * 2 + 1] + b1;
                if (EPI == 1) {
                    v0 = 0.5f * v0 * (1.f + erff(v0 * 0.70710678118654752f));
                    v1 = 0.5f * v1 * (1.f + erff(v1 * 0.70710678118654752f));
                }
                long long off = (long long)r * ldc + c0;
                if (EPI == 2) {
                    float gg0 = gate ? gate[c0]     : 1.f;
                    float gg1 = gate ? gate[c0 + 1] : 1.f;
                    float2 old = *(float2*)&C[off];
                    old.x += gg0 * v0;
                    old.y += gg1 * v1;
                    *(float2*)&C[off] = old;
                } else {
                    *(float2*)&C[off] = make_float2(v0, v1);
                }
            }
        }
    }
}

// ---------------------------------------------------------------------------
// Fused flash attention (tf32 mma, fp32 online softmax accumulators).
// Grid: (LQ/128, NH). Block: 256 threads (8 warps, 16 Q-rows each).
// q,k,v,o: row stride DM, head h at column h*HD. kv_len in {3072, 512}.
// Dynamic smem: Qs[128][68] | Ks[64][68] | Vs[64][72] | Ps[8][16][68]
// ---------------------------------------------------------------------------
#define FA_SMEM_WORDS (128*68 + 64*68 + 64*72 + 8*16*68)
#define FA_SMEM_BYTES (FA_SMEM_WORDS * 4)

__global__ __launch_bounds__(256)
void flash_kernel(const float* __restrict__ q, const float* __restrict__ k,
                  const float* __restrict__ v, float* __restrict__ o,
                  int kv_len)
{
    extern __shared__ unsigned sm[];
    unsigned* Qs = sm;                      // [128][68]
    unsigned* Ks = sm + 128 * 68;           // [64][68]
    unsigned* Vs = Ks + 64 * 68;            // [64][72]  (V row-major [kv][d])
    const int tid  = threadIdx.x;
    const int warp = tid >> 5, lane = tid & 31;
    const int gid  = lane >> 2, tig = lane & 3;
    unsigned* Ps = Vs + 64 * 72 + warp * (16 * 68);   // per-warp [16][68]

    const int q0 = blockIdx.x * 128;
    const int h  = blockIdx.y;
    const float* qh = q + h * HD;
    const float* kh = k + h * HD;
    const float* vh = v + h * HD;

    // load Q tile (128 x 64) as tf32
#pragma unroll
    for (int it = 0; it < 8; ++it) {
        int i = tid + it * 256;           // 0..2047 float4 index
        int r = i >> 4, c4 = (i & 15) << 2;
        float4 t = *(const float4*)(qh + (long long)(q0 + r) * DM + c4);
        unsigned* d = &Qs[r * 68 + c4];
        d[0] = f2tf32(t.x); d[1] = f2tf32(t.y); d[2] = f2tf32(t.z); d[3] = f2tf32(t.w);
    }

    float m0 = -1e30f, m1 = -1e30f, l0 = 0.f, l1 = 0.f;
    float Oacc[8][4];
#pragma unroll
    for (int nt = 0; nt < 8; nt++)
#pragma unroll
        for (int r = 0; r < 4; r++) Oacc[nt][r] = 0.f;

    const int wm = warp * 16;

    for (int kv0 = 0; kv0 < kv_len; kv0 += 64) {
        __syncthreads();   // prior-iter smem reads done before overwrite
        // load K,V tiles (64 x 64)
#pragma unroll
        for (int it = 0; it < 4; ++it) {
            int i = tid + it * 256;
            int r = i >> 4, c4 = (i & 15) << 2;
            float4 tk = *(const float4*)(kh + (long long)(kv0 + r) * DM + c4);
            float4 tv = *(const float4*)(vh + (long long)(kv0 + r) * DM + c4);
            unsigned* dk = &Ks[r * 68 + c4];
            dk[0] = f2tf32(tk.x); dk[1] = f2tf32(tk.y); dk[2] = f2tf32(tk.z); dk[3] = f2tf32(tk.w);
            unsigned* dv = &Vs[r * 72 + c4];
            dv[0] = f2tf32(tv.x); dv[1] = f2tf32(tv.y); dv[2] = f2tf32(tv.z); dv[3] = f2tf32(tv.w);
        }
        __syncthreads();

        // S = Q K^T  (warp: 16 x 64)
        float S[8][4];
#pragma unroll
        for (int nt = 0; nt < 8; nt++)
#pragma unroll
            for (int r = 0; r < 4; r++) S[nt][r] = 0.f;

#pragma unroll
        for (int kc = 0; kc < 64; kc += 8) {
            unsigned a[4];
            a[0] = Qs[(wm + gid    ) * 68 + kc + tig];
            a[1] = Qs[(wm + gid + 8) * 68 + kc + tig];
            a[2] = Qs[(wm + gid    ) * 68 + kc + tig + 4];
            a[3] = Qs[(wm + gid + 8) * 68 + kc + tig + 4];
#pragma unroll
            for (int nt = 0; nt < 8; nt++) {
                unsigned b[2];
                b[0] = Ks[(nt * 8 + gid) * 68 + kc + tig];
                b[1] = Ks[(nt * 8 + gid) * 68 + kc + tig + 4];
                mma_tf32(S[nt], a, b);
            }
        }

        // scale (exact: 2^-3) + row max (rows wm+gid and wm+gid+8)
        float mt0 = -1e30f, mt1 = -1e30f;
#pragma unroll
        for (int nt = 0; nt < 8; nt++) {
            S[nt][0] *= 0.125f; S[nt][1] *= 0.125f;
            S[nt][2] *= 0.125f; S[nt][3] *= 0.125f;
            mt0 = fmaxf(mt0, fmaxf(S[nt][0], S[nt][1]));
            mt1 = fmaxf(mt1, fmaxf(S[nt][2], S[nt][3]));
        }
#pragma unroll
        for (int off = 1; off < 4; off <<= 1) {
            mt0 = fmaxf(mt0, __shfl_xor_sync(0xFFFFFFFFu, mt0, off));
            mt1 = fmaxf(mt1, __shfl_xor_sync(0xFFFFFFFFu, mt1, off));
        }
        float mn0 = fmaxf(m0, mt0), mn1 = fmaxf(m1, mt1);
        float al0 = __expf(m0 - mn0), al1 = __expf(m1 - mn1);

        // P = exp(S - m), write to per-warp smem (tf32), partial row sums
        float s0 = 0.f, s1 = 0.f;
#pragma unroll
        for (int nt = 0; nt < 8; nt++) {
            float p0 = __expf(S[nt][0] - mn0);
            float p1 = __expf(S[nt][1] - mn0);
            float p2 = __expf(S[nt][2] - mn1);
            float p3 = __expf(S[nt][3] - mn1);
            s0 += p0 + p1; s1 += p2 + p3;
            int c = nt * 8 + tig * 2;
            Ps[ gid      * 68 + c    ] = f2tf32(p0);
            Ps[ gid      * 68 + c + 1] = f2tf32(p1);
            Ps[(gid + 8) * 68 + c    ] = f2tf32(p2);
            Ps[(gid + 8) * 68 + c + 1] = f2tf32(p3);
        }
#pragma unroll
        for (int off = 1; off < 4; off <<= 1) {
            s0 += __shfl_xor_sync(0xFFFFFFFFu, s0, off);
            s1 += __shfl_xor_sync(0xFFFFFFFFu, s1, off);
        }
        l0 = l0 * al0 + s0;
        l1 = l1 * al1 + s1;
        m0 = mn0; m1 = mn1;
#pragma unroll
        for (int nt = 0; nt < 8; nt++) {
            Oacc[nt][0] *= al0; Oacc[nt][1] *= al0;
            Oacc[nt][2] *= al1; Oacc[nt][3] *= al1;
        }
        __syncwarp();

        // O += P V   (P: 16 x 64 as A, V: 64 x 64 as B[k][n])
#pragma unroll
        for (int kc = 0; kc < 64; kc += 8) {
            unsigned a[4];
            a[0] = Ps[ gid      * 68 + kc + tig];
            a[1] = Ps[(gid + 8) * 68 + kc + tig];
            a[2] = Ps[ gid      * 68 + kc + tig + 4];
            a[3] = Ps[(gid + 8) * 68 + kc + tig + 4];
#pragma unroll
            for (int nt = 0; nt < 8; nt++) {
                unsigned b[2];
                b[0] = Vs[(kc + tig    ) * 72 + nt * 8 + gid];
                b[1] = Vs[(kc + tig + 4) * 72 + nt * 8 + gid];
                mma_tf32(Oacc[nt], a, b);
            }
        }
    }

    // write O / l
    float i0 = 1.f / l0, i1 = 1.f / l1;
    float* oh = o + h * HD;
    int r0 = q0 + wm + gid;
#pragma unroll
    for (int nt = 0; nt < 8; nt++) {
        int c = nt * 8 + tig * 2;
        *(float2*)&oh[(long long)r0 * DM + c] =
            make_float2(Oacc[nt][0] * i0, Oacc[nt][1] * i0);
        *(float2*)&oh[(long long)(r0 + 8) * DM + c] =
            make_float2(Oacc[nt][2] * i1, Oacc[nt][3] * i1);
    }
}

// ---------------------------------------------------------------------------
// LayerNorm (eps 1e-6) with optional adaLN modulation
// ---------------------------------------------------------------------------
__global__ __launch_bounds__(256)
void ln_kernel(const float* __restrict__ x, float* __restrict__ y,
               const float* __restrict__ sc, const float* __restrict__ sh)
{
    __shared__ float r1[256], r2[256];
    int row = blockIdx.x, tid = threadIdx.x;
    const float4* xr = (const float4*)(x + (long long)row * DM);
    float4 v = xr[tid];
    float s  = v.x + v.y + v.z + v.w;
    float sq = v.x * v.x + v.y * v.y + v.z * v.z + v.w * v.w;
    r1[tid] = s; r2[tid] = sq;
    __syncthreads();
    for (int st = 128; st > 0; st >>= 1) {
        if (tid < st) { r1[tid] += r1[tid + st]; r2[tid] += r2[tid + st]; }
        __syncthreads();
    }
    float mean = r1[0] * (1.f / DM);
    float var  = r2[0] * (1.f / DM) - mean * mean;
    float inv  = rsqrtf(var + 1e-6f);

    float a0 = (v.x - mean) * inv;
    float a1 = (v.y - mean) * inv;
    float a2 = (v.z - mean) * inv;
    float a3 = (v.w - mean) * inv;
    float4 o;
    int d = tid * 4;
    if (sc) {
        o.x = a0 * (1.f + sc[d + 0]) + sh[d + 0];
        o.y = a1 * (1.f + sc[d + 1]) + sh[d + 1];
        o.z = a2 * (1.f + sc[d + 2]) + sh[d + 2];
        o.w = a3 * (1.f + sc[d + 3]) + sh[d + 3];
    } else {
        o.x = a0; o.y = a1; o.z = a2; o.w = a3;
    }
    ((float4*)(y + (long long)row * DM))[tid] = o;
}

// ---------------------------------------------------------------------------
// 3D RoPE on q and k in place (rot_half form), head dim 64.
// ---------------------------------------------------------------------------
__global__ void rope_kernel(float* __restrict__ q, float* __restrict__ k,
                            const float* __restrict__ rope)
{
    int idx = blockIdx.x * blockDim.x + threadIdx.x;
    if (idx >= LQ * NH * 32) return;
    int d = idx & 31;
    int h = (idx >> 5) & (NH - 1);
    int l = idx >> 9;
    const float* rl = rope + (long long)l * HD;
    float c1 = cosf(rl[d]),      s1 = sinf(rl[d]);
    float c2 = cosf(rl[d + 32]), s2 = sinf(rl[d + 32]);
    long long o = (long long)l * DM + h * HD + d;
    float q1 = q[o], q2 = q[o + 32];
    q[o]      = q1 * c1 - q2 * s1;
    q[o + 32] = q2 * c2 + q1 * s2;
    float k1 = k[o], k2 = k[o + 32];
    k[o]      = k1 * c1 - k2 * s1;
    k[o + 32] = k2 * c2 + k1 * s2;
}

// ---------------------------------------------------------------------------
// adaLN GEMV: out[6144] = adaW_i @ t + adab_i. One warp per output row.
// ---------------------------------------------------------------------------
__global__ __launch_bounds__(256)
void ada_kernel(const float* __restrict__ W, const float* __restrict__ b,
                const float* __restrict__ t, float* __restrict__ out)
{
    int warp = threadIdx.x >> 5, lane = threadIdx.x & 31;
    int row = blockIdx.x * 8 + warp;
    const float* wr = W + (long long)row * DM;
    float s = 0.f;
    for (int c = lane; c < DM; c += 32) s = fmaf(wr[c], t[c], s);
#pragma unroll
    for (int o = 16; o > 0; o >>= 1) s += __shfl_xor_sync(0xFFFFFFFFu, s, o);
    if (lane == 0) out[row] = s + b[row];
}

// ---------------------------------------------------------------------------
// Host-side launch helpers
// ---------------------------------------------------------------------------
static inline void gemm_nt(const float* A, const float* B, const float* bias,
                           const float* gate, float* C, int M, int N, int K,
                           int lda, int ldb, int ldc, int epi)
{
    dim3 grid(N / 128, M / 128);
    if (epi == 0)      gemm_tc<0><<<grid, 256>>>(A, B, bias, gate, C, M, N, K, lda, ldb, ldc);
    else if (epi == 1) gemm_tc<1><<<grid, 256>>>(A, B, bias, gate, C, M, N, K, lda, ldb, ldc);
    else               gemm_tc<2><<<grid, 256>>>(A, B, bias, gate, C, M, N, K, lda, ldb, ldc);
}

extern "C" void kernel_launch(void* const* d_in, const int* in_sizes, int n_in,
                              void* d_out, int out_size)
{
    const float* x_in  = (const float*)d_in[0];
    const float* temb  = (const float*)d_in[1];
    const float* ctx   = (const float*)d_in[2];
    const float* rope  = (const float*)d_in[3];
    const float* adaW  = (const float*)d_in[4];
    const float* adab  = (const float*)d_in[5];
    const float* sqW   = (const float*)d_in[6];
    const float* skW   = (const float*)d_in[7];
    const float* svW   = (const float*)d_in[8];
    const float* soW   = (const float*)d_in[9];
    const float* sob   = (const float*)d_in[10];
    const float* cqW   = (const float*)d_in[11];
    const float* ckW   = (const float*)d_in[12];
    const float* cvW   = (const float*)d_in[13];
    const float* coW   = (const float*)d_in[14];
    const float* cob   = (const float*)d_in[15];
    const float* f1W   = (const float*)d_in[16];
    const float* f1b   = (const float*)d_in[17];
    const float* f2W   = (const float*)d_in[18];
    const float* f2b   = (const float*)d_in[19];

    float* x = (float*)d_out;   // x accumulates in the output buffer

    float *hx, *q, *k, *v, *o, *h1, *mods;
    cudaGetSymbolAddress((void**)&hx,   g_hx);
    cudaGetSymbolAddress((void**)&q,    g_q);
    cudaGetSymbolAddress((void**)&k,    g_k);
    cudaGetSymbolAddress((void**)&v,    g_v);
    cudaGetSymbolAddress((void**)&o,    g_o);
    cudaGetSymbolAddress((void**)&h1,   g_h1);
    cudaGetSymbolAddress((void**)&mods, g_mods);

    // allow >48KB dynamic smem for flash kernel (idempotent; not a stream op)
    cudaFuncSetAttribute(flash_kernel,
                         cudaFuncAttributeMaxDynamicSharedMemorySize,
                         FA_SMEM_BYTES);

    cudaMemcpyAsync(x, x_in, (size_t)LQ * DM * sizeof(float),
                    cudaMemcpyDeviceToDevice, 0);

    for (int i = 0; i < 2; i++) {
        const float* adaW_i = adaW + (long long)i * 6 * DM * DM;
        const float* adab_i = adab + (long long)i * 6 * DM;
        const float* sqW_i  = sqW + (long long)i * DM * DM;
        const float* skW_i  = skW + (long long)i * DM * DM;
        const float* svW_i  = svW + (long long)i * DM * DM;
        const float* soW_i  = soW + (long long)i * DM * DM;
        const float* sob_i  = sob + (long long)i * DM;
        const float* cqW_i  = cqW + (long long)i * DM * DM;
        const float* ckW_i  = ckW + (long long)i * DM * DM;
        const float* cvW_i  = cvW + (long long)i * DM * DM;
        const float* coW_i  = coW + (long long)i * DM * DM;
        const float* cob_i  = cob + (long long)i * DM;
        const float* f1W_i  = f1W + (long long)i * DFF * DM;
        const float* f1b_i  = f1b + (long long)i * DFF;
        const float* f2W_i  = f2W + (long long)i * DM * DFF;
        const float* f2b_i  = f2b + (long long)i * DM;

        // adaLN modulations
        ada_kernel<<<6 * DM / 8, 256>>>(adaW_i, adab_i, temb, mods);
        const float* sh_msa = mods + 0 * DM;
        const float* sc_msa = mods + 1 * DM;
        const float* g_msa  = mods + 2 * DM;
        const float* sh_mlp = mods + 3 * DM;
        const float* sc_mlp = mods + 4 * DM;
        const float* g_mlp  = mods + 5 * DM;

        // ---- self attention ----
        ln_kernel<<<LQ, 256>>>(x, hx, sc_msa, sh_msa);
        gemm_nt(hx, sqW_i, nullptr, nullptr, q, LQ, DM, DM, DM, DM, DM, 0);
        gemm_nt(hx, skW_i, nullptr, nullptr, k, LQ, DM, DM, DM, DM, DM, 0);
        gemm_nt(hx, svW_i, nullptr, nullptr, v, LQ, DM, DM, DM, DM, DM, 0);
        rope_kernel<<<(LQ * NH * 32 + 255) / 256, 256>>>(q, k, rope);

        {
            dim3 fg(LQ / 128, NH);
            flash_kernel<<<fg, 256, FA_SMEM_BYTES>>>(q, k, v, o, LQ);
        }
        // x += g_msa * (O soW^T + sob)
        gemm_nt(o, soW_i, sob_i, g_msa, x, LQ, DM, DM, DM, DM, DM, 2);

        // ---- cross attention ----
        ln_kernel<<<LQ, 256>>>(x, hx, nullptr, nullptr);
        gemm_nt(hx,  cqW_i, nullptr, nullptr, q, LQ, DM, DM, DM, DM, DM, 0);
        gemm_nt(ctx, ckW_i, nullptr, nullptr, k, SC, DM, DM, DM, DM, DM, 0);
        gemm_nt(ctx, cvW_i, nullptr, nullptr, v, SC, DM, DM, DM, DM, DM, 0);
        {
            dim3 fg(LQ / 128, NH);
            flash_kernel<<<fg, 256, FA_SMEM_BYTES>>>(q, k, v, o, SC);
        }
        // x += O coW^T + cob  (no gate)
        gemm_nt(o, coW_i, cob_i, nullptr, x, LQ, DM, DM, DM, DM, DM, 2);

        // ---- MLP ----
        ln_kernel<<<LQ, 256>>>(x, hx, sc_mlp, sh_mlp);
        gemm_nt(hx, f1W_i, f1b_i, nullptr, h1, LQ, DFF, DM, DM, DM, DFF, 1);
        gemm_nt(h1, f2W_i, f2b_i, g_mlp, x, LQ, DM, DFF, DFF, DFF, DM, 2);
    }
}